// round 13
// baseline (speedup 1.0000x reference)
#include <cuda_runtime.h>
#include <cstdint>

// Problem constants (fixed by the reference: T=8, x shape [T*32, 128, 32, 32])
#define T_STEPS   8
#define BATCH     32
#define CHANNELS  128
#define HW        1024                      // 32*32
#define N_ELEM    (BATCH*CHANNELS*HW)       // 4,194,304 spatial positions
#define GRID1     1024                      // single wave; all blocks co-resident
#define SLABS_PER_BLOCK 4                   // slabs b, b+1024, b+2048, b+3072 share channel b%128

// Scratch (static device globals — no runtime allocation permitted).
// Barrier counters are MONOTONIC across graph replays (each replay consumes
// exactly GRID1 arrivals / 1 release) -> no reset, fully deterministic.
__device__ float    g_partials[GRID1];
__device__ float    g_scale;
__device__ unsigned g_arrive  = 0;
__device__ unsigned g_release = 0;

// L2 eviction policies (policy-register form works at 128-bit width).
__device__ __forceinline__ uint64_t make_policy_evict_first() {
    uint64_t p;
    asm("createpolicy.fractional.L2::evict_first.b64 %0, 1.0;" : "=l"(p));
    return p;
}
__device__ __forceinline__ uint64_t make_policy_evict_last() {
    uint64_t p;
    asm("createpolicy.fractional.L2::evict_last.b64 %0, 1.0;" : "=l"(p));
    return p;
}
// x: single-use stream -> evict_first (don't displace the resident output).
__device__ __forceinline__ float4 ld_stream(const float* p, uint64_t pol) {
    float4 v;
    asm volatile("ld.global.nc.L2::cache_hint.v4.f32 {%0,%1,%2,%3}, [%4], %5;"
                 : "=f"(v.x), "=f"(v.y), "=f"(v.z), "=f"(v.w)
                 : "l"(p), "l"(pol));
    return v;
}
// out: rewritten every replay, read once at the very end -> evict_last.
__device__ __forceinline__ void st_resident(float* p, float4 v, uint64_t pol) {
    asm volatile("st.global.L2::cache_hint.v4.f32 [%0], {%1,%2,%3,%4}, %5;"
                 :: "l"(p), "f"(v.x), "f"(v.y), "f"(v.z), "f"(v.w), "l"(pol)
                 : "memory");
}

// Block-wide deterministic sum (256 threads): shuffle tree + one smem hop.
__device__ __forceinline__ float block_sum_256(float v, float* ws) {
#pragma unroll
    for (int off = 16; off > 0; off >>= 1)
        v += __shfl_down_sync(0xFFFFFFFFu, v, off);
    const int wid = threadIdx.x >> 5;
    if ((threadIdx.x & 31) == 0) ws[wid] = v;
    __syncthreads();
    if (wid == 0) {
        v = (threadIdx.x < 8) ? ws[threadIdx.x] : 0.0f;
#pragma unroll
        for (int off = 4; off > 0; off >>= 1)
            v += __shfl_down_sync(0xFFFFFFFFu, v, off);
    }
    __syncthreads();
    return v;                 // valid in thread 0
}

// ---------------------------------------------------------------------------
// Fused persistent kernel with zero-duplication write overlap:
//   Phase A: read x + recurrence; thread-words with NO spikes (≈45%) write
//            their final all-zero outputs immediately (scale-independent),
//            overlapping the read stream. Spiking words defer.
//   Barrier: last arriver computes the global scalar scale.
//   Phase B: write only the spiking thread-words (≈55% of write bytes).
// Every output word is written exactly once -> no extra traffic.
// ---------------------------------------------------------------------------
__global__ __launch_bounds__(256, 8) void if_fused(const float* __restrict__ x,
                                                   const float* __restrict__ thresh,
                                                   float* __restrict__ out) {
    __shared__ uint32_t s_bits[SLABS_PER_BLOCK][256];   // packed spike bytes, 4 KiB
    __shared__ float    s_ws[8];
    __shared__ float    s_scale;
    __shared__ unsigned s_gen;
    __shared__ int      s_last;

    const float    thre      = __ldg(thresh);
    const uint64_t pol_first = make_policy_evict_first();
    const uint64_t pol_last  = make_policy_evict_last();
    const float4   zero4     = make_float4(0.0f, 0.0f, 0.0f, 0.0f);
    float local = 0.0f;

    // ---- Phase A: recurrence + early zero-word writes ----
#pragma unroll 1
    for (int k = 0; k < SLABS_PER_BLOCK; k++) {
        const int slab = blockIdx.x + k * GRID1;
        const int n    = slab * HW + threadIdx.x * 4;

        float4 xv[T_STEPS];
#pragma unroll
        for (int t = 0; t < T_STEPS; t++)
            xv[t] = ld_stream(x + (size_t)t * N_ELEM + n, pol_first);

        float    mem[4] = {0.5f * thre, 0.5f * thre, 0.5f * thre, 0.5f * thre};
        unsigned sb[4]  = {0u, 0u, 0u, 0u};

#pragma unroll
        for (int t = 0; t < T_STEPS; t++) {
            const float v[4] = {xv[t].x, xv[t].y, xv[t].z, xv[t].w};
#pragma unroll
            for (int j = 0; j < 4; j++) {
                mem[j] += v[j];
                if (mem[j] >= thre) {          // heaviside(mem - cur)
                    mem[j] -= thre;            // mem -= s*cur
                    sb[j]  |= (1u << t);
                }
            }
        }

        const uint32_t word = sb[0] | (sb[1] << 8) | (sb[2] << 16) | (sb[3] << 24);
        s_bits[k][threadIdx.x] = word;

        // No spikes in this thread-word -> final output is all zeros; write it
        // NOW, overlapped with the read stream (scale-independent, final).
        if (word == 0u) {
#pragma unroll
            for (int t = 0; t < T_STEPS; t++)
                st_resident(out + (size_t)t * N_ELEM + n, zero4, pol_last);
        }

        // Compensation pass -> per-element new_thre (cnt via popc).
#pragma unroll
        for (int j = 0; j < 4; j++) {
            const int   cnt = __popc(sb[j]);
            const float cv  = fminf((mem[j] - 0.5f * thre) + (float)cnt * thre,
                                    (float)T_STEPS * thre);
            if (cv > 0.0f && cnt > 0)
                local += cv / (float)cnt;
        }
    }

    const float total = block_sum_256(local, s_ws);

    // ---- Grid barrier (generation-counted, monotonic across replays) ----
    if (threadIdx.x == 0) {
        g_partials[blockIdx.x] = total;
        __threadfence();
        const unsigned old = atomicAdd(&g_arrive, 1u);
        s_gen  = old / GRID1;
        s_last = ((old % GRID1) == GRID1 - 1);
    }
    __syncthreads();

    if (s_last) {
        // Per-channel ub (channel = bid % 128, 8 partials each, fixed order),
        // masked diff, deterministic reduction -> scalar scale.
        float contrib = 0.0f;
        if (threadIdx.x < CHANNELS) {
            float s = 0.0f;
#pragma unroll
            for (int j = 0; j < GRID1 / CHANNELS; j++)
                s += g_partials[threadIdx.x + j * CHANNELS];
            const float ub = s / (float)(BATCH * HW);
            contrib = (thre > ub) ? (ub - thre) : 0.0f;
        }
        const float tot = block_sum_256(contrib, s_ws);
        if (threadIdx.x == 0) {
            g_scale = thre + 0.2f * tot / (float)CHANNELS;    // LR*2 = 0.2
            __threadfence();
            atomicAdd(&g_release, 1u);
        }
    }

    if (threadIdx.x == 0) {
        const unsigned target = s_gen + 1u;
        unsigned v;
        for (;;) {
            asm volatile("ld.acquire.gpu.u32 %0, [%1];" : "=r"(v) : "l"(&g_release));
            if (v >= target) break;
            __nanosleep(128);           // back off: don't steal LTS slots from
        }                               // straggler blocks still streaming
        s_scale = g_scale;
    }
    __syncthreads();

    // ---- Phase B: write only the spiking thread-words ----
    const float scale = s_scale;
#pragma unroll 1
    for (int k = 0; k < SLABS_PER_BLOCK; k++) {
        const uint32_t bits = s_bits[k][threadIdx.x];
        if (bits == 0u) continue;                       // already written in A

        const int slab = blockIdx.x + k * GRID1;
        const int n    = slab * HW + threadIdx.x * 4;

#pragma unroll
        for (int t = 0; t < T_STEPS; t++) {
            float4 o;
            o.x = ((bits >> (t))      & 1u) ? scale : 0.0f;
            o.y = ((bits >> (t + 8))  & 1u) ? scale : 0.0f;
            o.z = ((bits >> (t + 16)) & 1u) ? scale : 0.0f;
            o.w = ((bits >> (t + 24)) & 1u) ? scale : 0.0f;
            st_resident(out + (size_t)t * N_ELEM + n, o, pol_last);
        }
    }
}

// ---------------------------------------------------------------------------
extern "C" void kernel_launch(void* const* d_in, const int* in_sizes, int n_in,
                              void* d_out, int out_size) {
    const float* x      = (const float*)d_in[0];   // [T*B, C, H, W] fp32
    const float* thresh = (const float*)d_in[1];   // [1] fp32
    float*       out    = (float*)d_out;

    if_fused<<<GRID1, 256>>>(x, thresh, out);
}

// round 14
// speedup vs baseline: 1.9169x; 1.9169x over previous
#include <cuda_runtime.h>
#include <cstdint>

// Problem constants (fixed by the reference: T=8, x shape [T*32, 128, 32, 32])
#define T_STEPS   8
#define BATCH     32
#define CHANNELS  128
#define HW        1024                      // 32*32
#define N_ELEM    (BATCH*CHANNELS*HW)       // 4,194,304 spatial positions
#define GRID1     1024                      // single wave; all blocks co-resident
#define SLABS_PER_BLOCK 4                   // slabs b, b+1024, b+2048, b+3072 share channel b%128

// Scratch (static device globals — no runtime allocation permitted).
// g_arrive is MONOTONIC across graph replays (each replay adds exactly GRID1
// arrivals) -> no reset, fully deterministic.
__device__ float    g_partials[GRID1];
__device__ unsigned g_arrive = 0;

// L2 policy hint for single-use streaming loads (128-bit, policy-register form).
__device__ __forceinline__ uint64_t make_policy_evict_first() {
    uint64_t p;
    asm("createpolicy.fractional.L2::evict_first.b64 %0, 1.0;" : "=l"(p));
    return p;
}
__device__ __forceinline__ float4 ld_stream(const float* p, uint64_t pol) {
    float4 v;
    asm volatile("ld.global.nc.L2::cache_hint.v4.f32 {%0,%1,%2,%3}, [%4], %5;"
                 : "=f"(v.x), "=f"(v.y), "=f"(v.z), "=f"(v.w)
                 : "l"(p), "l"(pol));
    return v;
}
// 256-bit store with direct evict_last modifier (v8 required for direct form):
// output lines stay resident in L2 and are overwritten in place across replays.
__device__ __forceinline__ void st256_resident(float* p, const float* v) {
    asm volatile("st.global.L2::evict_last.v8.b32 [%0], {%1,%2,%3,%4,%5,%6,%7,%8};"
                 :: "l"(p),
                    "r"(__float_as_uint(v[0])), "r"(__float_as_uint(v[1])),
                    "r"(__float_as_uint(v[2])), "r"(__float_as_uint(v[3])),
                    "r"(__float_as_uint(v[4])), "r"(__float_as_uint(v[5])),
                    "r"(__float_as_uint(v[6])), "r"(__float_as_uint(v[7]))
                 : "memory");
}

// Block-wide deterministic sum (256 threads): shuffle tree + one smem hop.
__device__ __forceinline__ float block_sum_256(float v, float* ws) {
#pragma unroll
    for (int off = 16; off > 0; off >>= 1)
        v += __shfl_down_sync(0xFFFFFFFFu, v, off);
    const int wid = threadIdx.x >> 5;
    if ((threadIdx.x & 31) == 0) ws[wid] = v;
    __syncthreads();
    if (wid == 0) {
        v = (threadIdx.x < 8) ? ws[threadIdx.x] : 0.0f;
#pragma unroll
        for (int off = 4; off > 0; off >>= 1)
            v += __shfl_down_sync(0xFFFFFFFFu, v, off);
    }
    __syncthreads();
    return v;                 // valid in thread 0
}

// ---------------------------------------------------------------------------
// Fused persistent kernel: IF recurrence (hoisted MLP=8 loads) -> arrival-only
// grid barrier -> EVERY block redundantly computes the global scale from the
// 1024 partials in a fixed order (bitwise-identical everywhere; removes the
// serialized reduce+release+wakeup from the critical path) -> 256-bit stores.
// ---------------------------------------------------------------------------
__global__ __launch_bounds__(256, 8) void if_fused(const float* __restrict__ x,
                                                   const float* __restrict__ thresh,
                                                   float* __restrict__ out) {
    __shared__ uint32_t s_bits[SLABS_PER_BLOCK][256];   // packed spike bytes, 4 KiB
    __shared__ float    s_ws[8];
    __shared__ float    s_scale;
    __shared__ unsigned s_gen;

    const float    thre      = __ldg(thresh);
    const uint64_t pol_first = make_policy_evict_first();
    float local = 0.0f;

    // ---- Phase A: recurrence over 4 same-channel slabs ----
#pragma unroll 1
    for (int k = 0; k < SLABS_PER_BLOCK; k++) {
        const int slab = blockIdx.x + k * GRID1;
        const int n    = slab * HW + threadIdx.x * 4;

        float4 xv[T_STEPS];
#pragma unroll
        for (int t = 0; t < T_STEPS; t++)
            xv[t] = ld_stream(x + (size_t)t * N_ELEM + n, pol_first);

        float    mem[4] = {0.5f * thre, 0.5f * thre, 0.5f * thre, 0.5f * thre};
        unsigned sb[4]  = {0u, 0u, 0u, 0u};

#pragma unroll
        for (int t = 0; t < T_STEPS; t++) {
            const float v[4] = {xv[t].x, xv[t].y, xv[t].z, xv[t].w};
#pragma unroll
            for (int j = 0; j < 4; j++) {
                mem[j] += v[j];
                if (mem[j] >= thre) {          // heaviside(mem - cur)
                    mem[j] -= thre;            // mem -= s*cur
                    sb[j]  |= (1u << t);
                }
            }
        }

        s_bits[k][threadIdx.x] = sb[0] | (sb[1] << 8) | (sb[2] << 16) | (sb[3] << 24);

        // Compensation pass -> per-element new_thre (cnt via popc).
#pragma unroll
        for (int j = 0; j < 4; j++) {
            const int   cnt = __popc(sb[j]);
            const float cv  = fminf((mem[j] - 0.5f * thre) + (float)cnt * thre,
                                    (float)T_STEPS * thre);
            if (cv > 0.0f && cnt > 0)
                local += cv / (float)cnt;
        }
    }

    const float total = block_sum_256(local, s_ws);

    // ---- Arrival-only grid barrier (monotonic generations) ----
    if (threadIdx.x == 0) {
        g_partials[blockIdx.x] = total;
        __threadfence();
        const unsigned old = atomicAdd(&g_arrive, 1u);
        s_gen = old / GRID1;                    // this replay's generation
    }
    __syncthreads();
    if (threadIdx.x == 0) {
        const unsigned target = (s_gen + 1u) * GRID1;   // all arrivals in
        unsigned v;
        for (;;) {
            asm volatile("ld.acquire.gpu.u32 %0, [%1];" : "=r"(v)
                         : "l"(&g_arrive) : "memory");
            if (v >= target) break;
            __nanosleep(256);          // back off: don't steal LTS slots from
        }                              // straggler blocks still streaming
    }
    __syncthreads();

    // ---- Redundant local finalization (identical fixed order per block) ----
    {
        float contrib = 0.0f;
        if (threadIdx.x < CHANNELS) {
            float s = 0.0f;
#pragma unroll
            for (int j = 0; j < GRID1 / CHANNELS; j++)
                s += g_partials[threadIdx.x + j * CHANNELS];
            const float ub = s / (float)(BATCH * HW);
            contrib = (thre > ub) ? (ub - thre) : 0.0f;
        }
        const float tot = block_sum_256(contrib, s_ws);
        if (threadIdx.x == 0)
            s_scale = thre + 0.2f * tot / (float)CHANNELS;   // LR*2 = 0.2
    }
    __syncthreads();

    // ---- Phase B: expansion with 256-bit stores ----
    // Threads split 128/128 across a slab pair; each thread owns 8 consecutive
    // elements, reading the two adjacent phase-A bit-words from smem.
    const float scale = s_scale;
    const int   tl    = threadIdx.x & 127;       // lane within slab (8 elems each)
    const int   sub   = threadIdx.x >> 7;        // which slab of the pair

#pragma unroll 1
    for (int kp = 0; kp < SLABS_PER_BLOCK; kp += 2) {
        const int      k    = kp + sub;
        const int      slab = blockIdx.x + k * GRID1;
        const int      n    = slab * HW + tl * 8;
        const uint32_t b0   = s_bits[k][tl * 2 + 0];    // elems n..n+3
        const uint32_t b1   = s_bits[k][tl * 2 + 1];    // elems n+4..n+7

#pragma unroll
        for (int t = 0; t < T_STEPS; t++) {
            float o[8];
#pragma unroll
            for (int e = 0; e < 4; e++)
                o[e]     = ((b0 >> (t + 8 * e)) & 1u) ? scale : 0.0f;
#pragma unroll
            for (int e = 0; e < 4; e++)
                o[e + 4] = ((b1 >> (t + 8 * e)) & 1u) ? scale : 0.0f;
            st256_resident(out + (size_t)t * N_ELEM + n, o);
        }
    }
}

// ---------------------------------------------------------------------------
extern "C" void kernel_launch(void* const* d_in, const int* in_sizes, int n_in,
                              void* d_out, int out_size) {
    const float* x      = (const float*)d_in[0];   // [T*B, C, H, W] fp32
    const float* thresh = (const float*)d_in[1];   // [1] fp32
    float*       out    = (float*)d_out;

    if_fused<<<GRID1, 256>>>(x, thresh, out);
}

// round 16
// speedup vs baseline: 1.9332x; 1.0085x over previous
#include <cuda_runtime.h>
#include <cstdint>

// Problem constants (fixed by the reference: T=8, x shape [T*32, 128, 32, 32])
#define T_STEPS   8
#define BATCH     32
#define CHANNELS  128
#define HW        1024                      // 32*32
#define N_ELEM    (BATCH*CHANNELS*HW)       // 4,194,304 spatial positions
#define GRID1     1024                      // single wave; all blocks co-resident
#define SLABS_PER_BLOCK 4                   // slabs b, b+1024, b+2048, b+3072 share channel b%128
#define T_PINNED  5                         // timesteps 0..4 (80 MiB) pinned in L2

// Scratch (static device globals — no runtime allocation permitted).
// g_arrive is MONOTONIC across graph replays (each replay adds exactly GRID1
// arrivals) -> no reset, fully deterministic.
__device__ float    g_partials[GRID1];
__device__ unsigned g_arrive = 0;

// L2 policy hint for single-use streaming loads (128-bit, policy-register form).
__device__ __forceinline__ uint64_t make_policy_evict_first() {
    uint64_t p;
    asm("createpolicy.fractional.L2::evict_first.b64 %0, 1.0;" : "=l"(p));
    return p;
}
__device__ __forceinline__ float4 ld_stream(const float* p, uint64_t pol) {
    float4 v;
    asm volatile("ld.global.nc.L2::cache_hint.v4.f32 {%0,%1,%2,%3}, [%4], %5;"
                 : "=f"(v.x), "=f"(v.y), "=f"(v.z), "=f"(v.w)
                 : "l"(p), "l"(pol));
    return v;
}
// 256-bit store, L2-pinned (direct evict_last modifier requires v8 width).
// Used for the 80 MiB slice that genuinely FITS in L2 -> no write-backs.
__device__ __forceinline__ void st256_resident(float* p, const float* v) {
    asm volatile("st.global.L2::evict_last.v8.b32 [%0], {%1,%2,%3,%4,%5,%6,%7,%8};"
                 :: "l"(p),
                    "r"(__float_as_uint(v[0])), "r"(__float_as_uint(v[1])),
                    "r"(__float_as_uint(v[2])), "r"(__float_as_uint(v[3])),
                    "r"(__float_as_uint(v[4])), "r"(__float_as_uint(v[5])),
                    "r"(__float_as_uint(v[6])), "r"(__float_as_uint(v[7]))
                 : "memory");
}
// 256-bit store, default policy (streams through; avoids thrashing the pinned set).
__device__ __forceinline__ void st256_normal(float* p, const float* v) {
    asm volatile("st.global.v8.b32 [%0], {%1,%2,%3,%4,%5,%6,%7,%8};"
                 :: "l"(p),
                    "r"(__float_as_uint(v[0])), "r"(__float_as_uint(v[1])),
                    "r"(__float_as_uint(v[2])), "r"(__float_as_uint(v[3])),
                    "r"(__float_as_uint(v[4])), "r"(__float_as_uint(v[5])),
                    "r"(__float_as_uint(v[6])), "r"(__float_as_uint(v[7]))
                 : "memory");
}

// Block-wide deterministic sum (256 threads): shuffle tree + one smem hop.
__device__ __forceinline__ float block_sum_256(float v, float* ws) {
#pragma unroll
    for (int off = 16; off > 0; off >>= 1)
        v += __shfl_down_sync(0xFFFFFFFFu, v, off);
    const int wid = threadIdx.x >> 5;
    if ((threadIdx.x & 31) == 0) ws[wid] = v;
    __syncthreads();
    if (wid == 0) {
        v = (threadIdx.x < 8) ? ws[threadIdx.x] : 0.0f;
#pragma unroll
        for (int off = 4; off > 0; off >>= 1)
            v += __shfl_down_sync(0xFFFFFFFFu, v, off);
    }
    __syncthreads();
    return v;                 // valid in thread 0
}

// ---------------------------------------------------------------------------
// Fused persistent kernel: IF recurrence (hoisted MLP=8 loads) -> arrival-only
// grid barrier -> redundant per-block scale finalization (bitwise-identical,
// fixed order) -> expansion with 256-bit stores, output split 80 MiB pinned /
// 48 MiB streamed so the pinned set actually fits in L2 (no thrash).
// ---------------------------------------------------------------------------
__global__ __launch_bounds__(256, 8) void if_fused(const float* __restrict__ x,
                                                   const float* __restrict__ thresh,
                                                   float* __restrict__ out) {
    __shared__ uint32_t s_bits[SLABS_PER_BLOCK][256];   // packed spike bytes, 4 KiB
    __shared__ float    s_ws[8];
    __shared__ float    s_scale;
    __shared__ unsigned s_gen;

    const float    thre      = __ldg(thresh);
    const uint64_t pol_first = make_policy_evict_first();
    float local = 0.0f;

    // ---- Phase A: recurrence over 4 same-channel slabs ----
#pragma unroll 1
    for (int k = 0; k < SLABS_PER_BLOCK; k++) {
        const int slab = blockIdx.x + k * GRID1;
        const int n    = slab * HW + threadIdx.x * 4;

        float4 xv[T_STEPS];
#pragma unroll
        for (int t = 0; t < T_STEPS; t++)
            xv[t] = ld_stream(x + (size_t)t * N_ELEM + n, pol_first);

        float    mem[4] = {0.5f * thre, 0.5f * thre, 0.5f * thre, 0.5f * thre};
        unsigned sb[4]  = {0u, 0u, 0u, 0u};

#pragma unroll
        for (int t = 0; t < T_STEPS; t++) {
            const float v[4] = {xv[t].x, xv[t].y, xv[t].z, xv[t].w};
#pragma unroll
            for (int j = 0; j < 4; j++) {
                mem[j] += v[j];
                if (mem[j] >= thre) {          // heaviside(mem - cur)
                    mem[j] -= thre;            // mem -= s*cur
                    sb[j]  |= (1u << t);
                }
            }
        }

        s_bits[k][threadIdx.x] = sb[0] | (sb[1] << 8) | (sb[2] << 16) | (sb[3] << 24);

        // Compensation pass -> per-element new_thre (cnt via popc).
#pragma unroll
        for (int j = 0; j < 4; j++) {
            const int   cnt = __popc(sb[j]);
            const float cv  = fminf((mem[j] - 0.5f * thre) + (float)cnt * thre,
                                    (float)T_STEPS * thre);
            if (cv > 0.0f && cnt > 0)
                local += cv / (float)cnt;
        }
    }

    const float total = block_sum_256(local, s_ws);

    // ---- Arrival-only grid barrier (monotonic generations) ----
    if (threadIdx.x == 0) {
        g_partials[blockIdx.x] = total;
        __threadfence();
        const unsigned old = atomicAdd(&g_arrive, 1u);
        s_gen = old / GRID1;                    // this replay's generation
    }
    __syncthreads();
    if (threadIdx.x == 0) {
        const unsigned target = (s_gen + 1u) * GRID1;   // all arrivals in
        unsigned v;
        for (;;) {
            asm volatile("ld.acquire.gpu.u32 %0, [%1];" : "=r"(v)
                         : "l"(&g_arrive) : "memory");
            if (v >= target) break;
            __nanosleep(256);          // back off: don't steal LTS slots from
        }                              // straggler blocks still streaming
    }
    __syncthreads();

    // ---- Redundant local finalization (identical fixed order per block) ----
    {
        float contrib = 0.0f;
        if (threadIdx.x < CHANNELS) {
            float s = 0.0f;
#pragma unroll
            for (int j = 0; j < GRID1 / CHANNELS; j++)
                s += g_partials[threadIdx.x + j * CHANNELS];
            const float ub = s / (float)(BATCH * HW);
            contrib = (thre > ub) ? (ub - thre) : 0.0f;
        }
        const float tot = block_sum_256(contrib, s_ws);
        if (threadIdx.x == 0)
            s_scale = thre + 0.2f * tot / (float)CHANNELS;   // LR*2 = 0.2
    }
    __syncthreads();

    // ---- Phase B: expansion with 256-bit stores (split L2 policy) ----
    // Threads split 128/128 across a slab pair; each thread owns 8 consecutive
    // elements, reading the two adjacent phase-A bit-words from smem.
    const float scale = s_scale;
    const int   tl    = threadIdx.x & 127;       // lane within slab (8 elems each)
    const int   sub   = threadIdx.x >> 7;        // which slab of the pair

#pragma unroll 1
    for (int kp = 0; kp < SLABS_PER_BLOCK; kp += 2) {
        const int      k    = kp + sub;
        const int      slab = blockIdx.x + k * GRID1;
        const int      n    = slab * HW + tl * 8;
        const uint32_t b0   = s_bits[k][tl * 2 + 0];    // elems n..n+3
        const uint32_t b1   = s_bits[k][tl * 2 + 1];    // elems n+4..n+7

#pragma unroll
        for (int t = 0; t < T_STEPS; t++) {
            float o[8];
#pragma unroll
            for (int e = 0; e < 4; e++)
                o[e]     = ((b0 >> (t + 8 * e)) & 1u) ? scale : 0.0f;
#pragma unroll
            for (int e = 0; e < 4; e++)
                o[e + 4] = ((b1 >> (t + 8 * e)) & 1u) ? scale : 0.0f;
            if (t < T_PINNED)
                st256_resident(out + (size_t)t * N_ELEM + n, o);  // 80 MiB pinned
            else
                st256_normal(out + (size_t)t * N_ELEM + n, o);    // 48 MiB streamed
        }
    }
}

// ---------------------------------------------------------------------------
extern "C" void kernel_launch(void* const* d_in, const int* in_sizes, int n_in,
                              void* d_out, int out_size) {
    const float* x      = (const float*)d_in[0];   // [T*B, C, H, W] fp32
    const float* thresh = (const float*)d_in[1];   // [1] fp32
    float*       out    = (float*)d_out;

    if_fused<<<GRID1, 256>>>(x, thresh, out);
}